// round 3
// baseline (speedup 1.0000x reference)
#include <cuda_runtime.h>

#define BATCH 128
#define SEQ   2000
#define EMB   50
#define VOCAB 1000000
#define SPLIT 4
#define CHUNK (SEQ / SPLIT)      // 500 tokens per block
#define WARPS 8
#define THREADS (WARPS * 32)
#define HALF_EMB 25              // 25 float2 per row

// Per-block partial pooled sums: [SPLIT][BATCH][25] float2.
__device__ float2 g_partial[SPLIT * BATCH * HALF_EMB];
// 1 if indices are int64 (stride 2 in 32-bit words), 0 if int32.
__device__ int g_idx_is64;

// Deterministic dtype sniff: int64 values in [-1, 1e6) have every odd 32-bit
// word == 0 (or 0xFFFFFFFF for -1). For an int32 index array the odd words are
// themselves random indices in [0, 1e6) — probability all 128 are 0/-1 is ~0.
__global__ void detect_kernel(const unsigned int* __restrict__ tw)
{
    int is64 = 1;
    for (int i = 0; i < 128; i++) {
        const unsigned int hi = tw[2 * i + 1];
        if (hi != 0u && hi != 0xFFFFFFFFu) { is64 = 0; break; }
    }
    g_idx_is64 = is64;
}

__global__ __launch_bounds__(THREADS) void accum_kernel(
    const int* __restrict__ t32, const float* __restrict__ emb)
{
    const int b     = blockIdx.y;
    const int chunk = blockIdx.x;
    const int warp  = threadIdx.x >> 5;
    const int lane  = threadIdx.x & 31;

    // Index stride in 32-bit words (1 for int32, 2 for int64 low-word reads).
    const int stride = g_idx_is64 ? 2 : 1;
    const int* trow = t32 + ((long long)b * SEQ + (long long)chunk * CHUNK) * stride;

    const bool active = (lane < HALF_EMB);
    const int  foff   = 2 * lane;          // float offset within a row

    float2 acc0 = make_float2(0.f, 0.f);
    float2 acc1 = make_float2(0.f, 0.f);

    int s = warp;
    for (; s + WARPS < CHUNK; s += 2 * WARPS) {
        const int v0 = trow[s * stride];              // warp-uniform broadcast
        const int v1 = trow[(s + WARPS) * stride];
        if (active) {
            if ((unsigned)v0 < (unsigned)VOCAB) {
                const float2 e =
                    *reinterpret_cast<const float2*>(emb + (long long)v0 * EMB + foff);
                acc0.x += e.x; acc0.y += e.y;
            }
            if ((unsigned)v1 < (unsigned)VOCAB) {
                const float2 e =
                    *reinterpret_cast<const float2*>(emb + (long long)v1 * EMB + foff);
                acc1.x += e.x; acc1.y += e.y;
            }
        }
    }
    for (; s < CHUNK; s += WARPS) {
        const int v = trow[s * stride];
        if (active && (unsigned)v < (unsigned)VOCAB) {
            const float2 e =
                *reinterpret_cast<const float2*>(emb + (long long)v * EMB + foff);
            acc0.x += e.x; acc0.y += e.y;
        }
    }
    acc0.x += acc1.x;
    acc0.y += acc1.y;

    __shared__ float2 red[WARPS][HALF_EMB];
    if (active) red[warp][lane] = acc0;
    __syncthreads();

    if (threadIdx.x < HALF_EMB) {
        float2 sum = red[0][threadIdx.x];
        #pragma unroll
        for (int w = 1; w < WARPS; w++) {
            sum.x += red[w][threadIdx.x].x;
            sum.y += red[w][threadIdx.x].y;
        }
        g_partial[(chunk * BATCH + b) * HALF_EMB + threadIdx.x] = sum;
    }
}

__global__ __launch_bounds__(128) void finalize_kernel(
    const float* __restrict__ W, const float* __restrict__ bias,
    float* __restrict__ out)
{
    const int b = threadIdx.x;     // one thread per batch row
    if (b >= BATCH) return;

    float a0 = bias[0];
    float a1 = bias[1];
    const float scale = 1.0f / (float)BATCH;   // reference divides by len(t)==BATCH

    #pragma unroll
    for (int j = 0; j < HALF_EMB; j++) {
        float2 p = g_partial[(0 * BATCH + b) * HALF_EMB + j];
        #pragma unroll
        for (int sp = 1; sp < SPLIT; sp++) {
            const float2 q = g_partial[(sp * BATCH + b) * HALF_EMB + j];
            p.x += q.x; p.y += q.y;
        }
        p.x *= scale; p.y *= scale;
        a0 += p.x * W[2 * j]       + p.y * W[2 * j + 1];
        a1 += p.x * W[EMB + 2 * j] + p.y * W[EMB + 2 * j + 1];
    }
    out[2 * b + 0] = fmaxf(a0, 0.0f);
    out[2 * b + 1] = fmaxf(a1, 0.0f);
}

extern "C" void kernel_launch(void* const* d_in, const int* in_sizes, int n_in,
                              void* d_out, int out_size)
{
    const int*   t32 = (const int*)d_in[0];        // int32 OR int64 [128, 2000]
    const float* emb = (const float*)d_in[1];      // f32 [1e6, 50]
    const float* W   = (const float*)d_in[2];      // f32 [2, 50]
    const float* bia = (const float*)d_in[3];      // f32 [2]
    float*       out = (float*)d_out;              // f32 [128, 2]

    detect_kernel<<<1, 1>>>((const unsigned int*)d_in[0]);
    dim3 grid(SPLIT, BATCH);
    accum_kernel<<<grid, THREADS>>>(t32, emb);
    finalize_kernel<<<1, 128>>>(W, bia, out);
}